// round 15
// baseline (speedup 1.0000x reference)
#include <cuda_runtime.h>
#include <cuda_fp16.h>
#include <math_constants.h>
#include <cstdint>

#define NN 40000
#define EE 640000
#define HH 8
#define DD 128
#define CAP 96
#define BLK_M 64
#define NBLK (NN / BLK_M)     // 625 exactly

// ---------------- device scratch ----------------
__device__ __half g_xh[NN * DD];         // transformed features, fp16 (kE consumer)
__device__ float g_al[NN * HH];
__device__ float g_ar[NN * HH];
__device__ int   g_deg[NN];
__device__ int2  g_sw[(size_t)NN * CAP];
__device__ unsigned char g_Bh[65536];    // W^T fp16, swizzled; rows 0-127=lin, 128-255=res

// smem layout (dynamic): A 16K | B 64K = 80KB
#define SM_A 0
#define SM_B 16384
#define SM_TOTAL 81920

__device__ __forceinline__ uint32_t sw_off(int r, int k) {
    return (uint32_t)(r * 256 + ((((k >> 3) ^ (r & 7)) << 4)) + (k & 7) * 2);
}
__device__ __forceinline__ uint32_t smem_u32(const void* p) {
    uint32_t a;
    asm("{ .reg .u64 t; cvta.to.shared.u64 t, %1; cvt.u32.u64 %0, t; }" : "=r"(a) : "l"(p));
    return a;
}
__device__ __forceinline__ void ldm4(uint32_t* r, uint32_t addr) {
    asm volatile("ldmatrix.sync.aligned.m8n8.x4.shared.b16 {%0,%1,%2,%3}, [%4];"
                 : "=r"(r[0]), "=r"(r[1]), "=r"(r[2]), "=r"(r[3]) : "r"(addr));
}
__device__ __forceinline__ void mma16816h(float* c, const uint32_t* a, uint32_t b0, uint32_t b1) {
    asm volatile("mma.sync.aligned.m16n8k16.row.col.f32.f16.f16.f32 "
                 "{%0,%1,%2,%3}, {%4,%5,%6,%7}, {%8,%9}, {%0,%1,%2,%3};"
                 : "+f"(c[0]), "+f"(c[1]), "+f"(c[2]), "+f"(c[3])
                 : "r"(a[0]), "r"(a[1]), "r"(a[2]), "r"(a[3]), "r"(b0), "r"(b1));
}

// ---------------- KW: transpose/swizzle W -> g_Bh (fp16) ----------------
__global__ void kW_prep(const float* __restrict__ Wlin, const float* __restrict__ Wres) {
    int i = blockIdx.x * blockDim.x + threadIdx.x;
    if (i >= 256 * DD) return;
    int n = i >> 7;
    int k = i & 127;
    float w = (n < 128) ? Wlin[k * 128 + n] : Wres[k * 128 + (n - 128)];
    *(__half*)(g_Bh + sw_off(n, k)) = __float2half_rn(w);
}

// ---------------- KA/KB: bucket build ----------------
__global__ void kA_zero() {
    int i = blockIdx.x * blockDim.x + threadIdx.x;
    if (i < NN) g_deg[i] = 0;
}
__global__ __launch_bounds__(256) void kB_bucket(
    const int* __restrict__ ei, const float* __restrict__ ew)
{
    int e = blockIdx.x * blockDim.x + threadIdx.x;
    if (e >= EE) return;
    const int src = __ldg(&ei[e]);
    const int dst = __ldg(&ei[EE + e]);
    const float w = __ldg(&ew[e]);
    int p = atomicAdd(&g_deg[dst], 1);
    if (p < CAP) g_sw[(size_t)dst * CAP + p] = make_int2(src, __float_as_int(w));
}

// ---------------- K1: fused single-pass fp16 HMMA dual GEMM (N=256) ----------
__global__ __launch_bounds__(256, 2) void k1_mma(
    const float* __restrict__ feat, const float* __restrict__ attl,
    const float* __restrict__ attr, float* __restrict__ out)
{
    extern __shared__ char sm[];
    const int tid = threadIdx.x;
    const int lane = tid & 31;
    const int wid = tid >> 5;
    const int row0 = blockIdx.x * BLK_M;

    // copy full pre-swizzled fp16 B (64KB: lin + res) into smem
    {
        const float4* s1 = (const float4*)g_Bh;
        float4* d1 = (float4*)(sm + SM_B);
        #pragma unroll
        for (int i = tid; i < 4096; i += 256) d1[i] = s1[i];
    }
    // convert A tile (64x128 fp32 -> fp16, swizzled) — done ONCE per tile now
    #pragma unroll
    for (int i = tid; i < 2048; i += 256) {
        const int m = i >> 5;
        const int k = (i & 31) * 4;
        float4 f = *(const float4*)&feat[(size_t)(row0 + m) * DD + k];
        __half2 h01 = __floats2half2_rn(f.x, f.y);
        __half2 h23 = __floats2half2_rn(f.z, f.w);
        const uint32_t o = sw_off(m, k);
        *(uint2*)(sm + SM_A + o) = make_uint2(*(uint32_t*)&h01, *(uint32_t*)&h23);
    }
    __syncthreads();

    const int wm = wid & 1;            // 0..1 -> 32-row group
    const int wn = wid >> 1;           // 0..3 -> 64-col group
    const int rm = wm * 32;
    const int cn = wn * 64;
    const uint32_t sb = smem_u32(sm);
    const uint32_t arow = sb + SM_A + (uint32_t)(rm + (lane & 15)) * 256;
    const uint32_t brow = sb + SM_B + (uint32_t)(cn + (lane & 15)) * 256;
    const uint32_t sext = (uint32_t)(lane >> 4);
    const uint32_t x7 = (uint32_t)(lane & 7);

    float c[2][8][4];
    #pragma unroll
    for (int i = 0; i < 2; i++)
        #pragma unroll
        for (int j = 0; j < 8; j++)
            #pragma unroll
            for (int q = 0; q < 4; q++) c[i][j][q] = 0.f;

    #pragma unroll
    for (int ks = 0; ks < 8; ks++) {
        const uint32_t coff = (((uint32_t)(2 * ks) + sext) ^ x7) << 4;
        uint32_t a0[4], a1[4], b[4][4];
        ldm4(a0, arow + coff);
        ldm4(a1, arow + 4096 + coff);
        ldm4(b[0], brow + coff);
        ldm4(b[1], brow + 4096 + coff);
        ldm4(b[2], brow + 8192 + coff);
        ldm4(b[3], brow + 12288 + coff);
        #pragma unroll
        for (int j = 0; j < 4; j++) {
            mma16816h(c[0][2 * j],     a0, b[j][0], b[j][2]);
            mma16816h(c[0][2 * j + 1], a0, b[j][1], b[j][3]);
            mma16816h(c[1][2 * j],     a1, b[j][0], b[j][2]);
            mma16816h(c[1][2 * j + 1], a1, b[j][1], b[j][3]);
        }
    }

    // epilogue (R7 structure): wn 0,1 -> x half (g_xh + alphas); wn 2,3 -> res
    const int g = lane >> 2;
    const int t = lane & 3;
    if (cn < 128) {
        float al[16], ar[16];
        #pragma unroll
        for (int nt = 0; nt < 8; nt++) {
            al[2 * nt]     = __ldg(&attl[cn + nt * 8 + 2 * t]);
            al[2 * nt + 1] = __ldg(&attl[cn + nt * 8 + 2 * t + 1]);
            ar[2 * nt]     = __ldg(&attr[cn + nt * 8 + 2 * t]);
            ar[2 * nt + 1] = __ldg(&attr[cn + nt * 8 + 2 * t + 1]);
        }
        #pragma unroll
        for (int mt = 0; mt < 2; mt++) {
            #pragma unroll
            for (int half = 0; half < 2; half++) {
                const int row = row0 + rm + mt * 16 + g + half * 8;
                #pragma unroll
                for (int nt = 0; nt < 8; nt++) {
                    __half2 hx = __floats2half2_rn(c[mt][nt][half * 2],
                                                   c[mt][nt][half * 2 + 1]);
                    *(__half2*)&g_xh[(size_t)row * DD + cn + nt * 8 + 2 * t] = hx;
                }
                #pragma unroll
                for (int h = 0; h < 4; h++) {
                    float dl = c[mt][2 * h][half * 2]     * al[4 * h]
                             + c[mt][2 * h][half * 2 + 1] * al[4 * h + 1]
                             + c[mt][2 * h + 1][half * 2]     * al[4 * h + 2]
                             + c[mt][2 * h + 1][half * 2 + 1] * al[4 * h + 3];
                    float dr = c[mt][2 * h][half * 2]     * ar[4 * h]
                             + c[mt][2 * h][half * 2 + 1] * ar[4 * h + 1]
                             + c[mt][2 * h + 1][half * 2]     * ar[4 * h + 2]
                             + c[mt][2 * h + 1][half * 2 + 1] * ar[4 * h + 3];
                    dl += __shfl_xor_sync(0xffffffffu, dl, 1);
                    dl += __shfl_xor_sync(0xffffffffu, dl, 2);
                    dr += __shfl_xor_sync(0xffffffffu, dr, 1);
                    dr += __shfl_xor_sync(0xffffffffu, dr, 2);
                    if (t == 0) {
                        g_al[row * HH + (cn >> 4) + h] = dl;
                        g_ar[row * HH + (cn >> 4) + h] = dr;
                    }
                }
            }
        }
    } else {
        #pragma unroll
        for (int mt = 0; mt < 2; mt++) {
            #pragma unroll
            for (int half = 0; half < 2; half++) {
                const int row = row0 + rm + mt * 16 + g + half * 8;
                #pragma unroll
                for (int nt = 0; nt < 8; nt++) {
                    *(float2*)&out[(size_t)row * DD + (cn - 128) + nt * 8 + 2 * t] =
                        make_float2(c[mt][nt][half * 2], c[mt][nt][half * 2 + 1]);
                }
            }
        }
    }
}

// ---------------- KE: 8-edge full chunks + 4-edge tail (unchanged) ----------
__device__ __forceinline__ unsigned long long pk2(float a, float b) {
    unsigned long long r;
    asm("mov.b64 %0, {%1,%2};" : "=l"(r) : "f"(a), "f"(b));
    return r;
}
__device__ __forceinline__ void fma2(unsigned long long& d, unsigned long long a, unsigned long long b) {
    asm("fma.rn.f32x2 %0, %1, %2, %0;" : "+l"(d) : "l"(a), "l"(b));
}
__device__ __forceinline__ float2 up2(unsigned long long v) {
    float2 r;
    asm("mov.b64 {%0,%1}, %2;" : "=f"(r.x), "=f"(r.y) : "l"(v));
    return r;
}

__global__ __launch_bounds__(256) void kE_gather(float* __restrict__ out)
{
    const int nd = blockIdx.x * 8 + (threadIdx.x >> 5);
    const int q = threadIdx.x & 31;
    const int cnt = min(g_deg[nd], CAP);
    const int h8 = q & 7;
    const int eg = q >> 3;
    const int hl = q >> 2;
    const float arh = g_ar[nd * HH + h8];
    const int2* __restrict__ sw = &g_sw[(size_t)nd * CAP];

    unsigned long long acc0 = 0ull, acc1 = 0ull;
    float s = 0.f;

    int i = 0;
    for (; i + 8 <= cnt; i += 8) {
        const int2 swA = sw[i + eg];
        const int2 swB = sw[i + 4 + eg];

        const int s0 = __shfl_sync(0xffffffffu, swA.x, 0);
        const int s1 = __shfl_sync(0xffffffffu, swA.x, 8);
        const int s2 = __shfl_sync(0xffffffffu, swA.x, 16);
        const int s3 = __shfl_sync(0xffffffffu, swA.x, 24);
        const int s4 = __shfl_sync(0xffffffffu, swB.x, 0);
        const int s5 = __shfl_sync(0xffffffffu, swB.x, 8);
        const int s6 = __shfl_sync(0xffffffffu, swB.x, 16);
        const int s7 = __shfl_sync(0xffffffffu, swB.x, 24);
        const uint2 x0 = *(const uint2*)&g_xh[(size_t)s0 * DD + q * 4];
        const uint2 x1 = *(const uint2*)&g_xh[(size_t)s1 * DD + q * 4];
        const uint2 x2 = *(const uint2*)&g_xh[(size_t)s2 * DD + q * 4];
        const uint2 x3 = *(const uint2*)&g_xh[(size_t)s3 * DD + q * 4];
        const uint2 x4 = *(const uint2*)&g_xh[(size_t)s4 * DD + q * 4];
        const uint2 x5 = *(const uint2*)&g_xh[(size_t)s5 * DD + q * 4];
        const uint2 x6 = *(const uint2*)&g_xh[(size_t)s6 * DD + q * 4];
        const uint2 x7 = *(const uint2*)&g_xh[(size_t)s7 * DD + q * 4];

        float vA = __int_as_float(swA.y) * (g_al[swA.x * HH + h8] + arh);
        vA = fmaxf(vA, 0.2f * vA);
        const float exA = __expf(vA);
        float vB = __int_as_float(swB.y) * (g_al[swB.x * HH + h8] + arh);
        vB = fmaxf(vB, 0.2f * vB);
        const float exB = __expf(vB);
        s += exA + exB;

        const float e0 = __shfl_sync(0xffffffffu, exA, hl);
        const float e1 = __shfl_sync(0xffffffffu, exA, 8 + hl);
        const float e2 = __shfl_sync(0xffffffffu, exA, 16 + hl);
        const float e3 = __shfl_sync(0xffffffffu, exA, 24 + hl);
        const float e4 = __shfl_sync(0xffffffffu, exB, hl);
        const float e5 = __shfl_sync(0xffffffffu, exB, 8 + hl);
        const float e6 = __shfl_sync(0xffffffffu, exB, 16 + hl);
        const float e7 = __shfl_sync(0xffffffffu, exB, 24 + hl);

        float2 f;
        unsigned long long d;
        d = pk2(e0, e0);
        f = __half22float2(*(const __half2*)&x0.x); fma2(acc0, pk2(f.x, f.y), d);
        f = __half22float2(*(const __half2*)&x0.y); fma2(acc1, pk2(f.x, f.y), d);
        d = pk2(e1, e1);
        f = __half22float2(*(const __half2*)&x1.x); fma2(acc0, pk2(f.x, f.y), d);
        f = __half22float2(*(const __half2*)&x1.y); fma2(acc1, pk2(f.x, f.y), d);
        d = pk2(e2, e2);
        f = __half22float2(*(const __half2*)&x2.x); fma2(acc0, pk2(f.x, f.y), d);
        f = __half22float2(*(const __half2*)&x2.y); fma2(acc1, pk2(f.x, f.y), d);
        d = pk2(e3, e3);
        f = __half22float2(*(const __half2*)&x3.x); fma2(acc0, pk2(f.x, f.y), d);
        f = __half22float2(*(const __half2*)&x3.y); fma2(acc1, pk2(f.x, f.y), d);
        d = pk2(e4, e4);
        f = __half22float2(*(const __half2*)&x4.x); fma2(acc0, pk2(f.x, f.y), d);
        f = __half22float2(*(const __half2*)&x4.y); fma2(acc1, pk2(f.x, f.y), d);
        d = pk2(e5, e5);
        f = __half22float2(*(const __half2*)&x5.x); fma2(acc0, pk2(f.x, f.y), d);
        f = __half22float2(*(const __half2*)&x5.y); fma2(acc1, pk2(f.x, f.y), d);
        d = pk2(e6, e6);
        f = __half22float2(*(const __half2*)&x6.x); fma2(acc0, pk2(f.x, f.y), d);
        f = __half22float2(*(const __half2*)&x6.y); fma2(acc1, pk2(f.x, f.y), d);
        d = pk2(e7, e7);
        f = __half22float2(*(const __half2*)&x7.x); fma2(acc0, pk2(f.x, f.y), d);
        f = __half22float2(*(const __half2*)&x7.y); fma2(acc1, pk2(f.x, f.y), d);
    }

    for (; i < cnt; i += 4) {
        const int idx = i + eg;
        const bool valid = idx < cnt;
        const int idxc = valid ? idx : cnt - 1;
        const int2 swv = sw[idxc];
        const int src = swv.x;
        const float w = __int_as_float(swv.y);

        const int s0 = __shfl_sync(0xffffffffu, src, 0);
        const int s1 = __shfl_sync(0xffffffffu, src, 8);
        const int s2 = __shfl_sync(0xffffffffu, src, 16);
        const int s3 = __shfl_sync(0xffffffffu, src, 24);
        const uint2 x0 = *(const uint2*)&g_xh[(size_t)s0 * DD + q * 4];
        const uint2 x1 = *(const uint2*)&g_xh[(size_t)s1 * DD + q * 4];
        const uint2 x2 = *(const uint2*)&g_xh[(size_t)s2 * DD + q * 4];
        const uint2 x3 = *(const uint2*)&g_xh[(size_t)s3 * DD + q * 4];

        float v = w * (g_al[src * HH + h8] + arh);
        v = fmaxf(v, 0.2f * v);
        float ex = valid ? __expf(v) : 0.f;
        s += ex;

        const float e0 = __shfl_sync(0xffffffffu, ex, hl);
        const float e1 = __shfl_sync(0xffffffffu, ex, 8 + hl);
        const float e2 = __shfl_sync(0xffffffffu, ex, 16 + hl);
        const float e3 = __shfl_sync(0xffffffffu, ex, 24 + hl);

        float2 f;
        unsigned long long d;
        d = pk2(e0, e0);
        f = __half22float2(*(const __half2*)&x0.x); fma2(acc0, pk2(f.x, f.y), d);
        f = __half22float2(*(const __half2*)&x0.y); fma2(acc1, pk2(f.x, f.y), d);
        d = pk2(e1, e1);
        f = __half22float2(*(const __half2*)&x1.x); fma2(acc0, pk2(f.x, f.y), d);
        f = __half22float2(*(const __half2*)&x1.y); fma2(acc1, pk2(f.x, f.y), d);
        d = pk2(e2, e2);
        f = __half22float2(*(const __half2*)&x2.x); fma2(acc0, pk2(f.x, f.y), d);
        f = __half22float2(*(const __half2*)&x2.y); fma2(acc1, pk2(f.x, f.y), d);
        d = pk2(e3, e3);
        f = __half22float2(*(const __half2*)&x3.x); fma2(acc0, pk2(f.x, f.y), d);
        f = __half22float2(*(const __half2*)&x3.y); fma2(acc1, pk2(f.x, f.y), d);
    }

    s += __shfl_xor_sync(0xffffffffu, s, 8);
    s += __shfl_xor_sync(0xffffffffu, s, 16);
    const float sh = __shfl_sync(0xffffffffu, s, hl);
    const float inv = (sh > 0.f) ? __fdividef(1.f, sh) : 0.f;

    const float2 a01 = up2(acc0);
    const float2 a23 = up2(acc1);
    float a0 = a01.x * inv, a1 = a01.y * inv, a2 = a23.x * inv, a3 = a23.y * inv;
    a0 = (a0 > 0.f) ? a0 : (__expf(a0) - 1.f);
    a1 = (a1 > 0.f) ? a1 : (__expf(a1) - 1.f);
    a2 = (a2 > 0.f) ? a2 : (__expf(a2) - 1.f);
    a3 = (a3 > 0.f) ? a3 : (__expf(a3) - 1.f);

    const float4 rv = *(const float4*)&out[(size_t)nd * DD + q * 4];
    *(float4*)&out[(size_t)nd * DD + q * 4] =
        make_float4(a0 + rv.x, a1 + rv.y, a2 + rv.z, a3 + rv.w);
}

// ---------------- launch: fork bucket build onto a side stream ----------------
extern "C" void kernel_launch(void* const* d_in, const int* in_sizes, int n_in,
                              void* d_out, int out_size)
{
    const float* feat = (const float*)d_in[0];
    const int*   ei   = (const int*)d_in[1];
    const float* ew   = (const float*)d_in[2];
    const float* Wlin = (const float*)d_in[3];
    const float* attl = (const float*)d_in[4];
    const float* attr = (const float*)d_in[5];
    const float* Wres = (const float*)d_in[6];
    float* out = (float*)d_out;

    static cudaStream_t s2 = nullptr;
    static cudaEvent_t evFork = nullptr, evJoin = nullptr;
    if (s2 == nullptr) {   // created on the eager correctness call, before capture
        cudaStreamCreateWithFlags(&s2, cudaStreamNonBlocking);
        cudaEventCreateWithFlags(&evFork, cudaEventDisableTiming);
        cudaEventCreateWithFlags(&evJoin, cudaEventDisableTiming);
        cudaFuncSetAttribute(k1_mma, cudaFuncAttributeMaxDynamicSharedMemorySize, SM_TOTAL);
    }

    cudaEventRecord(evFork, 0);
    cudaStreamWaitEvent(s2, evFork, 0);
    kA_zero<<<(NN + 255) / 256, 256, 0, s2>>>();
    kB_bucket<<<(EE + 255) / 256, 256, 0, s2>>>(ei, ew);
    cudaEventRecord(evJoin, s2);

    kW_prep<<<(256 * DD + 255) / 256, 256>>>(Wlin, Wres);
    k1_mma<<<NBLK, 256, SM_TOTAL>>>(feat, attl, attr, out);

    cudaStreamWaitEvent(0, evJoin, 0);
    kE_gather<<<NN * 32 / 256, 256>>>(out);
}

// round 16
// speedup vs baseline: 1.0281x; 1.0281x over previous
#include <cuda_runtime.h>
#include <cuda_fp16.h>
#include <math_constants.h>
#include <cstdint>

#define NN 40000
#define EE 640000
#define HH 8
#define DD 128
#define CAP 96
#define BLK_M 64
#define NBLK (NN / BLK_M)     // 625 exactly

// ---------------- device scratch ----------------
__device__ __half g_xh[NN * DD];         // transformed features, fp16 (kE consumer)
__device__ float g_al[NN * HH];
__device__ float g_ar[NN * HH];
__device__ int   g_deg[NN];
__device__ int2  g_sw[(size_t)NN * CAP];
__device__ unsigned char g_Bh[65536];    // W^T fp16, swizzled; rows 0-127=lin, 128-255=res

// smem layout (dynamic): A 16K | B 32K = 48KB
#define SM_A 0
#define SM_B 16384
#define SM_TOTAL 49152

__device__ __forceinline__ uint32_t sw_off(int r, int k) {
    return (uint32_t)(r * 256 + ((((k >> 3) ^ (r & 7)) << 4)) + (k & 7) * 2);
}
__device__ __forceinline__ uint32_t smem_u32(const void* p) {
    uint32_t a;
    asm("{ .reg .u64 t; cvta.to.shared.u64 t, %1; cvt.u32.u64 %0, t; }" : "=r"(a) : "l"(p));
    return a;
}
__device__ __forceinline__ void ldm4(uint32_t* r, uint32_t addr) {
    asm volatile("ldmatrix.sync.aligned.m8n8.x4.shared.b16 {%0,%1,%2,%3}, [%4];"
                 : "=r"(r[0]), "=r"(r[1]), "=r"(r[2]), "=r"(r[3]) : "r"(addr));
}
__device__ __forceinline__ void mma16816h(float* c, const uint32_t* a, uint32_t b0, uint32_t b1) {
    asm volatile("mma.sync.aligned.m16n8k16.row.col.f32.f16.f16.f32 "
                 "{%0,%1,%2,%3}, {%4,%5,%6,%7}, {%8,%9}, {%0,%1,%2,%3};"
                 : "+f"(c[0]), "+f"(c[1]), "+f"(c[2]), "+f"(c[3])
                 : "r"(a[0]), "r"(a[1]), "r"(a[2]), "r"(a[3]), "r"(b0), "r"(b1));
}

// ---------------- KW: transpose/swizzle W -> g_Bh (fp16) ----------------
__global__ void kW_prep(const float* __restrict__ Wlin, const float* __restrict__ Wres) {
    int i = blockIdx.x * blockDim.x + threadIdx.x;
    if (i >= 256 * DD) return;
    int n = i >> 7;
    int k = i & 127;
    float w = (n < 128) ? Wlin[k * 128 + n] : Wres[k * 128 + (n - 128)];
    *(__half*)(g_Bh + sw_off(n, k)) = __float2half_rn(w);
}

// ---------------- KA/KB: bucket build ----------------
__global__ void kA_zero() {
    int i = blockIdx.x * blockDim.x + threadIdx.x;
    if (i < NN) g_deg[i] = 0;
}
__global__ __launch_bounds__(256) void kB_bucket(
    const int* __restrict__ ei, const float* __restrict__ ew)
{
    int e = blockIdx.x * blockDim.x + threadIdx.x;
    if (e >= EE) return;
    const int src = __ldg(&ei[e]);
    const int dst = __ldg(&ei[EE + e]);
    const float w = __ldg(&ew[e]);
    int p = atomicAdd(&g_deg[dst], 1);
    if (p < CAP) g_sw[(size_t)dst * CAP + p] = make_int2(src, __float_as_int(w));
}

// ---------------- K1: single-pass fp16 HMMA GEMM; y: 0=lin, 1=res -----------
// R14 structure; ONLY change: min-blocks 3 -> 4 (force 64-reg budget, 4 CTA/SM)
__global__ __launch_bounds__(256, 4) void k1_mma(
    const float* __restrict__ feat, const float* __restrict__ attl,
    const float* __restrict__ attr, float* __restrict__ out)
{
    extern __shared__ char sm[];
    const int tid = threadIdx.x;
    const int lane = tid & 31;
    const int wid = tid >> 5;
    const int row0 = blockIdx.x * BLK_M;
    const int sel = blockIdx.y;           // 0 = Wlin, 1 = Wres

    {
        const float4* s1 = (const float4*)(g_Bh + sel * 32768);
        float4* d1 = (float4*)(sm + SM_B);
        #pragma unroll
        for (int i = tid; i < 2048; i += 256) d1[i] = s1[i];
    }
    #pragma unroll
    for (int i = tid; i < 2048; i += 256) {
        const int m = i >> 5;
        const int k = (i & 31) * 4;
        float4 f = *(const float4*)&feat[(size_t)(row0 + m) * DD + k];
        __half2 h01 = __floats2half2_rn(f.x, f.y);
        __half2 h23 = __floats2half2_rn(f.z, f.w);
        const uint32_t o = sw_off(m, k);
        *(uint2*)(sm + SM_A + o) = make_uint2(*(uint32_t*)&h01, *(uint32_t*)&h23);
    }
    __syncthreads();

    const int wm = wid & 1;
    const int wn = wid >> 1;
    const int rm = wm * 32;
    const int cn = wn * 32;
    const uint32_t sb = smem_u32(sm);
    const uint32_t arow = sb + SM_A + (uint32_t)(rm + (lane & 15)) * 256;
    const uint32_t brow = sb + SM_B + (uint32_t)(cn + (lane & 15)) * 256;
    const uint32_t sext = (uint32_t)(lane >> 4);
    const uint32_t x7 = (uint32_t)(lane & 7);

    float c[2][4][4];
    #pragma unroll
    for (int i = 0; i < 2; i++)
        #pragma unroll
        for (int j = 0; j < 4; j++)
            #pragma unroll
            for (int q = 0; q < 4; q++) c[i][j][q] = 0.f;

    #pragma unroll
    for (int ks = 0; ks < 8; ks++) {
        const uint32_t coff = (((uint32_t)(2 * ks) + sext) ^ x7) << 4;
        uint32_t a0[4], a1[4], b[2][4];
        ldm4(a0, arow + coff);
        ldm4(a1, arow + 4096 + coff);
        ldm4(b[0], brow + coff);
        ldm4(b[1], brow + 4096 + coff);

        mma16816h(c[0][0], a0, b[0][0], b[0][2]);
        mma16816h(c[0][1], a0, b[0][1], b[0][3]);
        mma16816h(c[0][2], a0, b[1][0], b[1][2]);
        mma16816h(c[0][3], a0, b[1][1], b[1][3]);
        mma16816h(c[1][0], a1, b[0][0], b[0][2]);
        mma16816h(c[1][1], a1, b[0][1], b[0][3]);
        mma16816h(c[1][2], a1, b[1][0], b[1][2]);
        mma16816h(c[1][3], a1, b[1][1], b[1][3]);
    }

    const int g = lane >> 2;
    const int t = lane & 3;
    if (sel == 0) {
        float al[8], ar[8];
        #pragma unroll
        for (int nt = 0; nt < 4; nt++) {
            al[2 * nt]     = __ldg(&attl[cn + nt * 8 + 2 * t]);
            al[2 * nt + 1] = __ldg(&attl[cn + nt * 8 + 2 * t + 1]);
            ar[2 * nt]     = __ldg(&attr[cn + nt * 8 + 2 * t]);
            ar[2 * nt + 1] = __ldg(&attr[cn + nt * 8 + 2 * t + 1]);
        }
        #pragma unroll
        for (int mt = 0; mt < 2; mt++) {
            #pragma unroll
            for (int half = 0; half < 2; half++) {
                const int row = row0 + rm + mt * 16 + g + half * 8;
                #pragma unroll
                for (int nt = 0; nt < 4; nt++) {
                    __half2 hx = __floats2half2_rn(c[mt][nt][half * 2],
                                                   c[mt][nt][half * 2 + 1]);
                    *(__half2*)&g_xh[(size_t)row * DD + cn + nt * 8 + 2 * t] = hx;
                }
                #pragma unroll
                for (int h = 0; h < 2; h++) {
                    float dl = c[mt][2 * h][half * 2]     * al[4 * h]
                             + c[mt][2 * h][half * 2 + 1] * al[4 * h + 1]
                             + c[mt][2 * h + 1][half * 2]     * al[4 * h + 2]
                             + c[mt][2 * h + 1][half * 2 + 1] * al[4 * h + 3];
                    float dr = c[mt][2 * h][half * 2]     * ar[4 * h]
                             + c[mt][2 * h][half * 2 + 1] * ar[4 * h + 1]
                             + c[mt][2 * h + 1][half * 2]     * ar[4 * h + 2]
                             + c[mt][2 * h + 1][half * 2 + 1] * ar[4 * h + 3];
                    dl += __shfl_xor_sync(0xffffffffu, dl, 1);
                    dl += __shfl_xor_sync(0xffffffffu, dl, 2);
                    dr += __shfl_xor_sync(0xffffffffu, dr, 1);
                    dr += __shfl_xor_sync(0xffffffffu, dr, 2);
                    if (t == 0) {
                        g_al[row * HH + (cn >> 4) + h] = dl;
                        g_ar[row * HH + (cn >> 4) + h] = dr;
                    }
                }
            }
        }
    } else {
        #pragma unroll
        for (int mt = 0; mt < 2; mt++) {
            #pragma unroll
            for (int half = 0; half < 2; half++) {
                const int row = row0 + rm + mt * 16 + g + half * 8;
                #pragma unroll
                for (int nt = 0; nt < 4; nt++) {
                    *(float2*)&out[(size_t)row * DD + cn + nt * 8 + 2 * t] =
                        make_float2(c[mt][nt][half * 2], c[mt][nt][half * 2 + 1]);
                }
            }
        }
    }
}

// ---------------- KE: 8-edge full chunks + 4-edge tail (R14, unchanged) ------
__device__ __forceinline__ unsigned long long pk2(float a, float b) {
    unsigned long long r;
    asm("mov.b64 %0, {%1,%2};" : "=l"(r) : "f"(a), "f"(b));
    return r;
}
__device__ __forceinline__ void fma2(unsigned long long& d, unsigned long long a, unsigned long long b) {
    asm("fma.rn.f32x2 %0, %1, %2, %0;" : "+l"(d) : "l"(a), "l"(b));
}
__device__ __forceinline__ float2 up2(unsigned long long v) {
    float2 r;
    asm("mov.b64 {%0,%1}, %2;" : "=f"(r.x), "=f"(r.y) : "l"(v));
    return r;
}

__global__ __launch_bounds__(256) void kE_gather(float* __restrict__ out)
{
    const int nd = blockIdx.x * 8 + (threadIdx.x >> 5);
    const int q = threadIdx.x & 31;
    const int cnt = min(g_deg[nd], CAP);
    const int h8 = q & 7;
    const int eg = q >> 3;
    const int hl = q >> 2;
    const float arh = g_ar[nd * HH + h8];
    const int2* __restrict__ sw = &g_sw[(size_t)nd * CAP];

    unsigned long long acc0 = 0ull, acc1 = 0ull;
    float s = 0.f;

    int i = 0;
    for (; i + 8 <= cnt; i += 8) {
        const int2 swA = sw[i + eg];
        const int2 swB = sw[i + 4 + eg];

        const int s0 = __shfl_sync(0xffffffffu, swA.x, 0);
        const int s1 = __shfl_sync(0xffffffffu, swA.x, 8);
        const int s2 = __shfl_sync(0xffffffffu, swA.x, 16);
        const int s3 = __shfl_sync(0xffffffffu, swA.x, 24);
        const int s4 = __shfl_sync(0xffffffffu, swB.x, 0);
        const int s5 = __shfl_sync(0xffffffffu, swB.x, 8);
        const int s6 = __shfl_sync(0xffffffffu, swB.x, 16);
        const int s7 = __shfl_sync(0xffffffffu, swB.x, 24);
        const uint2 x0 = *(const uint2*)&g_xh[(size_t)s0 * DD + q * 4];
        const uint2 x1 = *(const uint2*)&g_xh[(size_t)s1 * DD + q * 4];
        const uint2 x2 = *(const uint2*)&g_xh[(size_t)s2 * DD + q * 4];
        const uint2 x3 = *(const uint2*)&g_xh[(size_t)s3 * DD + q * 4];
        const uint2 x4 = *(const uint2*)&g_xh[(size_t)s4 * DD + q * 4];
        const uint2 x5 = *(const uint2*)&g_xh[(size_t)s5 * DD + q * 4];
        const uint2 x6 = *(const uint2*)&g_xh[(size_t)s6 * DD + q * 4];
        const uint2 x7 = *(const uint2*)&g_xh[(size_t)s7 * DD + q * 4];

        float vA = __int_as_float(swA.y) * (g_al[swA.x * HH + h8] + arh);
        vA = fmaxf(vA, 0.2f * vA);
        const float exA = __expf(vA);
        float vB = __int_as_float(swB.y) * (g_al[swB.x * HH + h8] + arh);
        vB = fmaxf(vB, 0.2f * vB);
        const float exB = __expf(vB);
        s += exA + exB;

        const float e0 = __shfl_sync(0xffffffffu, exA, hl);
        const float e1 = __shfl_sync(0xffffffffu, exA, 8 + hl);
        const float e2 = __shfl_sync(0xffffffffu, exA, 16 + hl);
        const float e3 = __shfl_sync(0xffffffffu, exA, 24 + hl);
        const float e4 = __shfl_sync(0xffffffffu, exB, hl);
        const float e5 = __shfl_sync(0xffffffffu, exB, 8 + hl);
        const float e6 = __shfl_sync(0xffffffffu, exB, 16 + hl);
        const float e7 = __shfl_sync(0xffffffffu, exB, 24 + hl);

        float2 f;
        unsigned long long d;
        d = pk2(e0, e0);
        f = __half22float2(*(const __half2*)&x0.x); fma2(acc0, pk2(f.x, f.y), d);
        f = __half22float2(*(const __half2*)&x0.y); fma2(acc1, pk2(f.x, f.y), d);
        d = pk2(e1, e1);
        f = __half22float2(*(const __half2*)&x1.x); fma2(acc0, pk2(f.x, f.y), d);
        f = __half22float2(*(const __half2*)&x1.y); fma2(acc1, pk2(f.x, f.y), d);
        d = pk2(e2, e2);
        f = __half22float2(*(const __half2*)&x2.x); fma2(acc0, pk2(f.x, f.y), d);
        f = __half22float2(*(const __half2*)&x2.y); fma2(acc1, pk2(f.x, f.y), d);
        d = pk2(e3, e3);
        f = __half22float2(*(const __half2*)&x3.x); fma2(acc0, pk2(f.x, f.y), d);
        f = __half22float2(*(const __half2*)&x3.y); fma2(acc1, pk2(f.x, f.y), d);
        d = pk2(e4, e4);
        f = __half22float2(*(const __half2*)&x4.x); fma2(acc0, pk2(f.x, f.y), d);
        f = __half22float2(*(const __half2*)&x4.y); fma2(acc1, pk2(f.x, f.y), d);
        d = pk2(e5, e5);
        f = __half22float2(*(const __half2*)&x5.x); fma2(acc0, pk2(f.x, f.y), d);
        f = __half22float2(*(const __half2*)&x5.y); fma2(acc1, pk2(f.x, f.y), d);
        d = pk2(e6, e6);
        f = __half22float2(*(const __half2*)&x6.x); fma2(acc0, pk2(f.x, f.y), d);
        f = __half22float2(*(const __half2*)&x6.y); fma2(acc1, pk2(f.x, f.y), d);
        d = pk2(e7, e7);
        f = __half22float2(*(const __half2*)&x7.x); fma2(acc0, pk2(f.x, f.y), d);
        f = __half22float2(*(const __half2*)&x7.y); fma2(acc1, pk2(f.x, f.y), d);
    }

    for (; i < cnt; i += 4) {
        const int idx = i + eg;
        const bool valid = idx < cnt;
        const int idxc = valid ? idx : cnt - 1;
        const int2 swv = sw[idxc];
        const int src = swv.x;
        const float w = __int_as_float(swv.y);

        const int s0 = __shfl_sync(0xffffffffu, src, 0);
        const int s1 = __shfl_sync(0xffffffffu, src, 8);
        const int s2 = __shfl_sync(0xffffffffu, src, 16);
        const int s3 = __shfl_sync(0xffffffffu, src, 24);
        const uint2 x0 = *(const uint2*)&g_xh[(size_t)s0 * DD + q * 4];
        const uint2 x1 = *(const uint2*)&g_xh[(size_t)s1 * DD + q * 4];
        const uint2 x2 = *(const uint2*)&g_xh[(size_t)s2 * DD + q * 4];
        const uint2 x3 = *(const uint2*)&g_xh[(size_t)s3 * DD + q * 4];

        float v = w * (g_al[src * HH + h8] + arh);
        v = fmaxf(v, 0.2f * v);
        float ex = valid ? __expf(v) : 0.f;
        s += ex;

        const float e0 = __shfl_sync(0xffffffffu, ex, hl);
        const float e1 = __shfl_sync(0xffffffffu, ex, 8 + hl);
        const float e2 = __shfl_sync(0xffffffffu, ex, 16 + hl);
        const float e3 = __shfl_sync(0xffffffffu, ex, 24 + hl);

        float2 f;
        unsigned long long d;
        d = pk2(e0, e0);
        f = __half22float2(*(const __half2*)&x0.x); fma2(acc0, pk2(f.x, f.y), d);
        f = __half22float2(*(const __half2*)&x0.y); fma2(acc1, pk2(f.x, f.y), d);
        d = pk2(e1, e1);
        f = __half22float2(*(const __half2*)&x1.x); fma2(acc0, pk2(f.x, f.y), d);
        f = __half22float2(*(const __half2*)&x1.y); fma2(acc1, pk2(f.x, f.y), d);
        d = pk2(e2, e2);
        f = __half22float2(*(const __half2*)&x2.x); fma2(acc0, pk2(f.x, f.y), d);
        f = __half22float2(*(const __half2*)&x2.y); fma2(acc1, pk2(f.x, f.y), d);
        d = pk2(e3, e3);
        f = __half22float2(*(const __half2*)&x3.x); fma2(acc0, pk2(f.x, f.y), d);
        f = __half22float2(*(const __half2*)&x3.y); fma2(acc1, pk2(f.x, f.y), d);
    }

    s += __shfl_xor_sync(0xffffffffu, s, 8);
    s += __shfl_xor_sync(0xffffffffu, s, 16);
    const float sh = __shfl_sync(0xffffffffu, s, hl);
    const float inv = (sh > 0.f) ? __fdividef(1.f, sh) : 0.f;

    const float2 a01 = up2(acc0);
    const float2 a23 = up2(acc1);
    float a0 = a01.x * inv, a1 = a01.y * inv, a2 = a23.x * inv, a3 = a23.y * inv;
    a0 = (a0 > 0.f) ? a0 : (__expf(a0) - 1.f);
    a1 = (a1 > 0.f) ? a1 : (__expf(a1) - 1.f);
    a2 = (a2 > 0.f) ? a2 : (__expf(a2) - 1.f);
    a3 = (a3 > 0.f) ? a3 : (__expf(a3) - 1.f);

    const float4 rv = *(const float4*)&out[(size_t)nd * DD + q * 4];
    *(float4*)&out[(size_t)nd * DD + q * 4] =
        make_float4(a0 + rv.x, a1 + rv.y, a2 + rv.z, a3 + rv.w);
}

// ---------------- launch: fork bucket build onto a side stream ----------------
extern "C" void kernel_launch(void* const* d_in, const int* in_sizes, int n_in,
                              void* d_out, int out_size)
{
    const float* feat = (const float*)d_in[0];
    const int*   ei   = (const int*)d_in[1];
    const float* ew   = (const float*)d_in[2];
    const float* Wlin = (const float*)d_in[3];
    const float* attl = (const float*)d_in[4];
    const float* attr = (const float*)d_in[5];
    const float* Wres = (const float*)d_in[6];
    float* out = (float*)d_out;

    static cudaStream_t s2 = nullptr;
    static cudaEvent_t evFork = nullptr, evJoin = nullptr;
    if (s2 == nullptr) {   // created on the eager correctness call, before capture
        cudaStreamCreateWithFlags(&s2, cudaStreamNonBlocking);
        cudaEventCreateWithFlags(&evFork, cudaEventDisableTiming);
        cudaEventCreateWithFlags(&evJoin, cudaEventDisableTiming);
        cudaFuncSetAttribute(k1_mma, cudaFuncAttributeMaxDynamicSharedMemorySize, SM_TOTAL);
    }

    cudaEventRecord(evFork, 0);
    cudaStreamWaitEvent(s2, evFork, 0);
    kA_zero<<<(NN + 255) / 256, 256, 0, s2>>>();
    kB_bucket<<<(EE + 255) / 256, 256, 0, s2>>>(ei, ew);
    cudaEventRecord(evJoin, s2);

    kW_prep<<<(256 * DD + 255) / 256, 256>>>(Wlin, Wres);
    k1_mma<<<dim3(NBLK, 2), 256, SM_TOTAL>>>(feat, attl, attr, out);

    cudaStreamWaitEvent(0, evJoin, 0);
    kE_gather<<<NN * 32 / 256, 256>>>(out);
}